// round 15
// baseline (speedup 1.0000x reference)
#include <cuda_runtime.h>
#include <cuda_fp16.h>
#include <cstdint>

#define HID   2048
#define NEXP  64
#define NTOK  16384
#define SINK_TOL 1e-4
#define MAX_ITERS 512
#define GRIDB 128
#define TPB   512
#define NW    16
#define TOKB  128          // 16384 = 128 * 128 exactly
#define BKC   64           // k-chunk (elems) -> 128 B fp16 rows (SW128 atom)
#define NCHUNK (HID / BKC) // 32
#define CSTRIDE 16         // colsum pad: 128 B per expert column
#define WSCALE 64.0f       // exact pow2 pre-scale of W (fp16 subnormal avoidance)
#define WUNSCALE 0.015625f // 1/64, exact

// per-buffer tile offsets (bytes); buffer = 48 KB, two buffers
#define OF_A1  0
#define OF_A2  16384
#define OF_B1  32768
#define OF_B2  40960
#define BUFSZ  49152
#define DSM_TOTAL (2 * BUFSZ)   // 98304 B dynamic smem

extern "C" __device__ float __nv_expf(float);

__device__ __forceinline__ float frcp_approx(float x) {
    float r; asm("rcp.approx.f32 %0,%1;" : "=f"(r) : "f"(x)); return r;
}
__device__ __forceinline__ uint32_t smem_u32(const void* p) {
    uint32_t a;
    asm("{ .reg .u64 t; cvta.to.shared.u64 t, %1; cvt.u32.u64 %0, t; }" : "=r"(a) : "l"(p));
    return a;
}
#define SWZ(off) ((off) ^ (((off) >> 3) & 0x70))

__device__ __forceinline__ void ldsm_x4(uint32_t* r, uint32_t addr) {
    asm volatile("ldmatrix.sync.aligned.m8n8.x4.shared.b16 {%0,%1,%2,%3}, [%4];"
                 : "=r"(r[0]), "=r"(r[1]), "=r"(r[2]), "=r"(r[3]) : "r"(addr));
}
__device__ __forceinline__ void mma_f16(float* c, const uint32_t* a, const uint32_t* b) {
    asm volatile("mma.sync.aligned.m16n8k16.row.col.f32.f16.f16.f32 "
                 "{%0,%1,%2,%3}, {%4,%5,%6,%7}, {%8,%9}, {%0,%1,%2,%3};"
                 : "+f"(c[0]), "+f"(c[1]), "+f"(c[2]), "+f"(c[3])
                 : "r"(a[0]), "r"(a[1]), "r"(a[2]), "r"(a[3]), "r"(b[0]), "r"(b[1]));
}

// Scratch (static device arrays — no allocations).
__device__ unsigned long long g_bar = 0ULL;                      // grid barrier
__device__ double g_colsum[MAX_ITERS * NEXP * CSTRIDE];          // padded colsums

__device__ __forceinline__ void grid_barrier()
{
    __syncthreads();
    if (threadIdx.x == 0) {
        __threadfence();
        unsigned long long my = atomicAdd(&g_bar, 1ULL);
        unsigned long long target = (my / GRIDB + 1ULL) * GRIDB;
        for (;;) {
            unsigned long long cur;
            asm volatile("ld.global.acquire.gpu.u64 %0, [%1];" : "=l"(cur) : "l"(&g_bar));
            if (cur >= target) break;
        }
    }
    __syncthreads();
}

__device__ __forceinline__ double warp_tree_add64(double s)
{
#pragma unroll
    for (int off = 16; off; off >>= 1)
        s += __shfl_xor_sync(0xffffffffu, s, off);
    return s;
}

// 2-way fp16 split of 8 f32 (optionally pre-scaled by exact pow2) via paired
// cvt.rn.f16x2 — per-lane rounding identical to scalar __float2half_rn, so
// tiles are bitwise identical to the scalar-split version.  Store 16B segs
// into two tiles `spacing` bytes apart.
__device__ __forceinline__ void split2_store(char* base, int spacing, uint32_t sw,
                                             float4 v0, float4 v1, float scale)
{
    float f[8] = {v0.x, v0.y, v0.z, v0.w, v1.x, v1.y, v1.z, v1.w};
    uint32_t q1[4], q2[4];
#pragma unroll
    for (int i = 0; i < 4; i++) {
        float2 p = make_float2(f[2 * i] * scale, f[2 * i + 1] * scale); // exact pow2
        __half2 x1 = __float22half2_rn(p);
        float2  b  = __half22float2(x1);                               // exact
        __half2 x2 = __float22half2_rn(make_float2(p.x - b.x, p.y - b.y));
        q1[i] = *(uint32_t*)&x1;
        q2[i] = *(uint32_t*)&x2;
    }
    *(uint4*)(base + sw)           = make_uint4(q1[0], q1[1], q1[2], q1[3]);
    *(uint4*)(base + spacing + sw) = make_uint4(q2[0], q2[1], q2[2], q2[3]);
}

// ---------------------------------------------------------------------------
__global__ void __launch_bounds__(TPB, 1)
fused_router_kernel(const float* __restrict__ X, const float* __restrict__ W,
                    float* __restrict__ out, int out_size)
{
    extern __shared__ char dsm[];
    __shared__ float  warp_part[NW][NEXP];
    __shared__ double d1d[NEXP], d1pd[NEXP];
    __shared__ float  d1f[NEXP];
    __shared__ double s_err;

    const int tid  = threadIdx.x;
    const int bid  = blockIdx.x;
    const int lane = tid & 31;
    const int w    = tid >> 5;
    const int tok0 = bid * TOKB;
    const uint32_t smb = smem_u32(dsm);
    float* Cs = (float*)dsm;    // overlays buf0 after GEMM completes

    // zero this launch's colsum slots
    for (int i = bid * TPB + tid; i < MAX_ITERS * NEXP; i += GRIDB * TPB)
        g_colsum[(size_t)i * CSTRIDE] = 0.0;

    // ================= phase A: producer/consumer fp16-2-split HMMA ========
    // 3 products: x2w1, x1w2, x1w1 (x2w2 dropped: ~1.4e-7 logit noise)
    const bool producer = (w >= 8);
    const int mt = (w & 7) >> 1;          // m-tile 0..3 (32 rows each)
    const int nh = w & 1;                 // n-half 0..1 (32 cols)

    uint32_t aconst[2], amask[2];
#pragma unroll
    for (int mi = 0; mi < 2; mi++) {
        int arow = mt * 32 + mi * 16 + (lane & 15);
        aconst[mi] = (uint32_t)(arow * 128);
        amask[mi]  = (uint32_t)((arow & 7) << 4);
    }
    const uint32_t akoff = (uint32_t)((lane >> 4) * 16);
    uint32_t bconst4[2];
#pragma unroll
    for (int jj = 0; jj < 2; jj++) {
        int brow = nh * 32 + (jj * 2 + ((lane >> 4) & 1)) * 8 + (lane & 7);
        bconst4[jj] = (uint32_t)(brow * 128);
    }
    const uint32_t bmask = (uint32_t)((lane & 7) << 4);
    const uint32_t bkoff = (uint32_t)(((lane >> 3) & 1) * 16);

    const uint32_t SA[2] = {OF_A1, OF_A2};
    const uint32_t SB[2] = {OF_B1, OF_B2};
    // products smallest-first: x2w1, x1w2, x1w1
    const int PAI[3] = {1, 0, 0};
    const int PBI[3] = {0, 1, 0};

    const int ptid = tid & 255;
    uint32_t asw_p[4]; size_t aoff_p[4];
    uint32_t bsw_p[2]; size_t boff_p[2];
#pragma unroll
    for (int j = 0; j < 4; j++) {
        int seg = ptid + j * 256;
        int row = seg >> 3, kq = (seg & 7) * 8;
        asw_p[j]  = SWZ((uint32_t)(row * 128 + kq * 2));
        aoff_p[j] = (size_t)(tok0 + row) * HID + kq;
    }
#pragma unroll
    for (int j = 0; j < 2; j++) {
        int seg = ptid + j * 256;
        int row = seg >> 3, kq = (seg & 7) * 8;
        bsw_p[j]  = SWZ((uint32_t)(row * 128 + kq * 2));
        boff_p[j] = (size_t)row * HID + kq;
    }

    float4 av[4][2], bvv[2][2];
    if (producer) {   // prefetch chunk 0
#pragma unroll
        for (int j = 0; j < 4; j++) {
            av[j][0] = *(const float4*)(X + aoff_p[j]);
            av[j][1] = *(const float4*)(X + aoff_p[j] + 4);
        }
#pragma unroll
        for (int j = 0; j < 2; j++) {
            bvv[j][0] = *(const float4*)(W + boff_p[j]);
            bvv[j][1] = *(const float4*)(W + boff_p[j] + 4);
        }
    }

    float hi[2][4][4];
#pragma unroll
    for (int mi = 0; mi < 2; mi++)
#pragma unroll
        for (int j = 0; j < 4; j++)
#pragma unroll
            for (int q = 0; q < 4; q++) hi[mi][j][q] = 0.f;

    for (int it = 0; it <= NCHUNK; it++) {
        if (producer) {
            if (it < NCHUNK) {
                char* base = dsm + (it & 1) * BUFSZ;
#pragma unroll
                for (int j = 0; j < 4; j++)
                    split2_store(base + OF_A1, 16384, asw_p[j], av[j][0], av[j][1], 1.0f);
#pragma unroll
                for (int j = 0; j < 2; j++)
                    split2_store(base + OF_B1, 8192, bsw_p[j], bvv[j][0], bvv[j][1], WSCALE);
                if (it + 1 < NCHUNK) {
                    int k0 = (it + 1) * BKC;
#pragma unroll
                    for (int j = 0; j < 4; j++) {
                        av[j][0] = *(const float4*)(X + aoff_p[j] + k0);
                        av[j][1] = *(const float4*)(X + aoff_p[j] + k0 + 4);
                    }
#pragma unroll
                    for (int j = 0; j < 2; j++) {
                        bvv[j][0] = *(const float4*)(W + boff_p[j] + k0);
                        bvv[j][1] = *(const float4*)(W + boff_p[j] + k0 + 4);
                    }
                }
            }
        } else if (it >= 1) {
            const uint32_t bb = smb + (uint32_t)(((it - 1) & 1) * BUFSZ);
            float accf[2][4][4];
#pragma unroll
            for (int mi = 0; mi < 2; mi++)
#pragma unroll
                for (int j = 0; j < 4; j++)
#pragma unroll
                    for (int q = 0; q < 4; q++) accf[mi][j][q] = 0.f;
#pragma unroll
            for (int ks = 0; ks < 4; ks++) {
                uint32_t kb_a = (uint32_t)(ks * 32) + akoff;
                uint32_t kb_b = (uint32_t)(ks * 32) + bkoff;
                uint32_t afr[2][2][4];      // [split][mi]
                uint32_t bfr[2][2][4];      // [split][jj]
#pragma unroll
                for (int s = 0; s < 2; s++) {
#pragma unroll
                    for (int mi = 0; mi < 2; mi++)
                        ldsm_x4(afr[s][mi], bb + SA[s] + aconst[mi] + (kb_a ^ amask[mi]));
#pragma unroll
                    for (int jj = 0; jj < 2; jj++)
                        ldsm_x4(bfr[s][jj], bb + SB[s] + bconst4[jj] + (kb_b ^ bmask));
                }
#pragma unroll
                for (int p = 0; p < 3; p++)
#pragma unroll
                    for (int mi = 0; mi < 2; mi++)
#pragma unroll
                        for (int j = 0; j < 4; j++)
                            mma_f16(accf[mi][j], afr[PAI[p]][mi],
                                    &bfr[PBI[p]][j >> 1][(j & 1) * 2]);
            }
#pragma unroll
            for (int mi = 0; mi < 2; mi++)
#pragma unroll
                for (int j = 0; j < 4; j++)
#pragma unroll
                    for (int q = 0; q < 4; q++) hi[mi][j][q] += accf[mi][j][q];
        }
        __syncthreads();
    }

    // epilogue: unscale (exact pow2) then exp(logits) into Cs (overlays buf0)
    if (!producer) {
#pragma unroll
        for (int mi = 0; mi < 2; mi++) {
            int r0 = mt * 32 + mi * 16 + (lane >> 2);
#pragma unroll
            for (int j = 0; j < 4; j++) {
                int cc = nh * 32 + j * 8 + (lane & 3) * 2;
                float2 v0 = make_float2(__nv_expf(hi[mi][j][0] * WUNSCALE),
                                        __nv_expf(hi[mi][j][1] * WUNSCALE));
                float2 v1 = make_float2(__nv_expf(hi[mi][j][2] * WUNSCALE),
                                        __nv_expf(hi[mi][j][3] * WUNSCALE));
                *(float2*)&Cs[r0 * NEXP + cc]       = v0;
                *(float2*)&Cs[(r0 + 8) * NEXP + cc] = v1;
            }
        }
    }
    if (tid < NEXP) { d1d[tid] = 1.0; d1pd[tid] = 1.0; d1f[tid] = 1.f; }
    grid_barrier();   // Cs ready; colsum zeros globally visible

    // ================= phase B: Sinkhorn iterations (as R13) ===============
    const float  INVN0F = 1.0f / (float)NTOK;   // 2^-14 exact
    const float  INVN1F = 0.015625f;            // 2^-6 exact
    const float  EPSF   = 1e-8f;
    const double INVN1D = 1.0 / (double)NEXP;
    const double EPSD   = (double)1e-8f;
    const int    esl    = (tid < NEXP) ? ((tid + (bid << 2)) & 63) : 0;

    for (int it = 0; it < MAX_ITERS; it++) {
        float d1a = d1f[lane];
        float d1c = d1f[lane + 32];
        float p0 = 0.f, p1 = 0.f;
        {   // 8-way interleaved shuffle trees; original accumulation order
            float c0[8], c1[8], s[8];
#pragma unroll
            for (int q = 0; q < 8; q++) {
                int t = w + q * NW;
                c0[q] = Cs[t * NEXP + lane];
                c1[q] = Cs[t * NEXP + lane + 32];
                s[q]  = fmaf(d1a, c0[q], d1c * c1[q]);
            }
#pragma unroll
            for (int off = 16; off; off >>= 1)
#pragma unroll
                for (int q = 0; q < 8; q++)
                    s[q] += __shfl_xor_sync(0xffffffffu, s[q], off);
#pragma unroll
            for (int q = 0; q < 8; q++) {
                float d0 = frcp_approx(s[q] + EPSF) * INVN0F;
                p0 = fmaf(d0, c0[q], p0);
                p1 = fmaf(d0, c1[q], p1);
            }
        }
        warp_part[w][lane]      = p0;
        warp_part[w][lane + 32] = p1;
        __syncthreads();
        if (tid < NEXP) {
            double sum = 0.0;
#pragma unroll
            for (int ww = 0; ww < NW; ww++) sum += (double)warp_part[ww][esl];
            atomicAdd(&g_colsum[((size_t)it * NEXP + esl) * CSTRIDE], sum);
        }
        grid_barrier();

        if (w == 0) {
            double cs0 = g_colsum[((size_t)it * NEXP + lane) * CSTRIDE];
            double cs1 = g_colsum[((size_t)it * NEXP + lane + 32) * CSTRIDE];
            // fast f32 mirror first — unblocks the next row pass ASAP
            d1f[lane]      = frcp_approx((float)cs0 + EPSF) * INVN1F;
            d1f[lane + 32] = frcp_approx((float)cs1 + EPSF) * INVN1F;
            // f64 master via rcp + 2 Newton steps (~1 ulp)
            double x0 = cs0 + EPSD, x1 = cs1 + EPSD;
            double r0 = (double)frcp_approx((float)x0);
            double r1 = (double)frcp_approx((float)x1);
            r0 = r0 * (2.0 - x0 * r0); r0 = r0 * (2.0 - x0 * r0);
            r1 = r1 * (2.0 - x1 * r1); r1 = r1 * (2.0 - x1 * r1);
            double v0 = INVN1D * r0, v1 = INVN1D * r1;
            double o0 = d1d[lane], o1 = d1d[lane + 32];
            double s  = warp_tree_add64(fabs(o0 - v0) + fabs(o1 - v1));
            d1pd[lane]      = o0;  d1pd[lane + 32] = o1;
            d1d[lane]       = v0;  d1d[lane + 32]  = v1;
            if (lane == 0) s_err = s * INVN1D;
        }
        __syncthreads();
        if (s_err <= SINK_TOL) break;
    }

    // ================= phase C: top-2 (fp64) + softmax-gather ==============
    const double INVN0D = 1.0 / (double)NTOK;
    double d1a = d1d[lane],  d1c = d1d[lane + 32];
    double dpa = d1pd[lane], dpc = d1pd[lane + 32];
    for (int t = w; t < TOKB; t += NW) {
        double c0 = (double)Cs[t * NEXP + lane];
        double c1 = (double)Cs[t * NEXP + lane + 32];
        double sr = warp_tree_add64(dpa * c0 + dpc * c1);
        double rs = warp_tree_add64(c0 + c1);
        double d0 = INVN0D / (sr + EPSD);
        double v0 = (d1a * c0) * d0;
        double v1 = (d1c * c1) * d0;

        double mv; int mi;
        if (v0 >= v1) { mv = v0; mi = lane; } else { mv = v1; mi = lane + 32; }
#pragma unroll
        for (int off = 16; off; off >>= 1) {
            double ov = __shfl_xor_sync(0xffffffffu, mv, off);
            int    oi = __shfl_xor_sync(0xffffffffu, mi, off);
            if (ov > mv || (ov == mv && oi < mi)) { mv = ov; mi = oi; }
        }
        double u0 = (lane      == mi) ? -1e308 : v0;
        double u1 = (lane + 32 == mi) ? -1e308 : v1;
        double mv2; int mi2;
        if (u0 >= u1) { mv2 = u0; mi2 = lane; } else { mv2 = u1; mi2 = lane + 32; }
#pragma unroll
        for (int off = 16; off; off >>= 1) {
            double ov = __shfl_xor_sync(0xffffffffu, mv2, off);
            int    oi = __shfl_xor_sync(0xffffffffu, mi2, off);
            if (ov > mv2 || (ov == mv2 && oi < mi2)) { mv2 = ov; mi2 = oi; }
        }

        if (lane == 0) {
            int tg = tok0 + t;
            float s0 = (float)((double)Cs[t * NEXP + mi]  / rs);
            float s1 = (float)((double)Cs[t * NEXP + mi2] / rs);
            if (out_size >= 4 * NTOK) {
                out[(size_t)tg * 2 + 0] = s0;
                out[(size_t)tg * 2 + 1] = s1;
                out[(size_t)2 * NTOK + tg * 2 + 0] = (float)mi;
                out[(size_t)2 * NTOK + tg * 2 + 1] = (float)mi2;
            } else {
                out[(size_t)tg * 2 + 0] = s0;
                out[(size_t)tg * 2 + 1] = s1;
            }
        }
    }
}

// ---------------------------------------------------------------------------
extern "C" void kernel_launch(void* const* d_in, const int* in_sizes, int n_in,
                              void* d_out, int out_size)
{
    const float* X = (const float*)d_in[0];
    const float* W = (const float*)d_in[1];
    if (n_in >= 2 && in_sizes[0] == NEXP * HID) {   // defensive input-order check
        X = (const float*)d_in[1];
        W = (const float*)d_in[0];
    }
    cudaFuncSetAttribute(fused_router_kernel,
                         cudaFuncAttributeMaxDynamicSharedMemorySize, DSM_TOTAL);
    fused_router_kernel<<<GRIDB, TPB, DSM_TOTAL>>>(X, W, (float*)d_out, out_size);
}

// round 16
// speedup vs baseline: 1.5429x; 1.5429x over previous
#include <cuda_runtime.h>
#include <cuda_fp16.h>
#include <cstdint>

#define HID   2048
#define NEXP  64
#define NTOK  16384
#define SINK_TOL 1e-4
#define MAX_ITERS 512
#define GRIDB 128
#define TPB   512
#define NW    16
#define TOKB  128          // 16384 = 128 * 128 exactly
#define BKC   64           // k-chunk (elems) -> 128 B fp16 rows (SW128 atom)
#define NCHUNK (HID / BKC) // 32
#define CSTRIDE 16         // colsum pad: 128 B per expert column
#define WSCALE 64.0f       // exact pow2 pre-scale of W (fp16 subnormal avoidance)
#define WUNSCALE 0.015625f // 1/64, exact

// per-buffer tile offsets (bytes); buffer = 48 KB, two buffers
#define OF_A1  0
#define OF_A2  16384
#define OF_B1  32768
#define OF_B2  40960
#define BUFSZ  49152
#define DSM_TOTAL (2 * BUFSZ)   // 98304 B dynamic smem

extern "C" __device__ float __nv_expf(float);

__device__ __forceinline__ float frcp_approx(float x) {
    float r; asm("rcp.approx.f32 %0,%1;" : "=f"(r) : "f"(x)); return r;
}
__device__ __forceinline__ uint32_t smem_u32(const void* p) {
    uint32_t a;
    asm("{ .reg .u64 t; cvta.to.shared.u64 t, %1; cvt.u32.u64 %0, t; }" : "=r"(a) : "l"(p));
    return a;
}
#define SWZ(off) ((off) ^ (((off) >> 3) & 0x70))

__device__ __forceinline__ void ldsm_x4(uint32_t* r, uint32_t addr) {
    asm volatile("ldmatrix.sync.aligned.m8n8.x4.shared.b16 {%0,%1,%2,%3}, [%4];"
                 : "=r"(r[0]), "=r"(r[1]), "=r"(r[2]), "=r"(r[3]) : "r"(addr));
}
__device__ __forceinline__ void mma_f16(float* c, const uint32_t* a, const uint32_t* b) {
    asm volatile("mma.sync.aligned.m16n8k16.row.col.f32.f16.f16.f32 "
                 "{%0,%1,%2,%3}, {%4,%5,%6,%7}, {%8,%9}, {%0,%1,%2,%3};"
                 : "+f"(c[0]), "+f"(c[1]), "+f"(c[2]), "+f"(c[3])
                 : "r"(a[0]), "r"(a[1]), "r"(a[2]), "r"(a[3]), "r"(b[0]), "r"(b[1]));
}

// Scratch (static device arrays — no allocations).
__device__ unsigned long long g_bar = 0ULL;                      // grid barrier
__device__ double g_colsum[MAX_ITERS * NEXP * CSTRIDE];          // padded colsums

__device__ __forceinline__ void grid_barrier()
{
    __syncthreads();
    if (threadIdx.x == 0) {
        __threadfence();
        unsigned long long my = atomicAdd(&g_bar, 1ULL);
        unsigned long long target = (my / GRIDB + 1ULL) * GRIDB;
        for (;;) {
            unsigned long long cur;
            asm volatile("ld.global.acquire.gpu.u64 %0, [%1];" : "=l"(cur) : "l"(&g_bar));
            if (cur >= target) break;
        }
    }
    __syncthreads();
}

__device__ __forceinline__ double warp_tree_add64(double s)
{
#pragma unroll
    for (int off = 16; off; off >>= 1)
        s += __shfl_xor_sync(0xffffffffu, s, off);
    return s;
}

// 2-way fp16 split of 8 f32 (optionally pre-scaled), store 16B segs into two
// tiles spaced `spacing` bytes apart.
__device__ __forceinline__ void split2_store(char* base, int spacing, uint32_t sw,
                                             float4 v0, float4 v1, float scale)
{
    float f[8] = {v0.x, v0.y, v0.z, v0.w, v1.x, v1.y, v1.z, v1.w};
    unsigned short h1[8], h2[8];
#pragma unroll
    for (int i = 0; i < 8; i++) {
        float a = f[i] * scale;                 // exact for pow2 scale
        __half x1 = __float2half_rn(a);
        float r1 = a - __half2float(x1);        // exact
        __half x2 = __float2half_rn(r1);
        h1[i] = __half_as_ushort(x1);
        h2[i] = __half_as_ushort(x2);
    }
    uint4 q;
    q.x = h1[0] | ((uint32_t)h1[1] << 16); q.y = h1[2] | ((uint32_t)h1[3] << 16);
    q.z = h1[4] | ((uint32_t)h1[5] << 16); q.w = h1[6] | ((uint32_t)h1[7] << 16);
    *(uint4*)(base + sw) = q;
    q.x = h2[0] | ((uint32_t)h2[1] << 16); q.y = h2[2] | ((uint32_t)h2[3] << 16);
    q.z = h2[4] | ((uint32_t)h2[5] << 16); q.w = h2[6] | ((uint32_t)h2[7] << 16);
    *(uint4*)(base + spacing + sw) = q;
}

// ---------------------------------------------------------------------------
__global__ void __launch_bounds__(TPB, 1)
fused_router_kernel(const float* __restrict__ X, const float* __restrict__ W,
                    float* __restrict__ out, int out_size)
{
    extern __shared__ char dsm[];
    __shared__ float  warp_part[NW][NEXP];
    __shared__ double d1d[NEXP], d1pd[NEXP];
    __shared__ float  d1f[NEXP];
    __shared__ double s_err;

    const int tid  = threadIdx.x;
    const int bid  = blockIdx.x;
    const int lane = tid & 31;
    const int w    = tid >> 5;
    const int tok0 = bid * TOKB;
    const uint32_t smb = smem_u32(dsm);
    float* Cs = (float*)dsm;    // overlays buf0 after GEMM completes

    // zero this launch's colsum slots
    for (int i = bid * TPB + tid; i < MAX_ITERS * NEXP; i += GRIDB * TPB)
        g_colsum[(size_t)i * CSTRIDE] = 0.0;

    // ================= phase A: producer/consumer fp16-2-split HMMA ========
    // 3 products: x2w1, x1w2, x1w1 (x2w2 dropped: ~1.4e-7 logit noise)
    const bool producer = (w >= 8);
    const int mt = (w & 7) >> 1;          // m-tile 0..3 (32 rows each)
    const int nh = w & 1;                 // n-half 0..1 (32 cols)

    uint32_t aconst[2], amask[2];
#pragma unroll
    for (int mi = 0; mi < 2; mi++) {
        int arow = mt * 32 + mi * 16 + (lane & 15);
        aconst[mi] = (uint32_t)(arow * 128);
        amask[mi]  = (uint32_t)((arow & 7) << 4);
    }
    const uint32_t akoff = (uint32_t)((lane >> 4) * 16);
    uint32_t bconst4[2];
#pragma unroll
    for (int jj = 0; jj < 2; jj++) {
        int brow = nh * 32 + (jj * 2 + ((lane >> 4) & 1)) * 8 + (lane & 7);
        bconst4[jj] = (uint32_t)(brow * 128);
    }
    const uint32_t bmask = (uint32_t)((lane & 7) << 4);
    const uint32_t bkoff = (uint32_t)(((lane >> 3) & 1) * 16);

    const uint32_t SA[2] = {OF_A1, OF_A2};
    const uint32_t SB[2] = {OF_B1, OF_B2};
    // products smallest-first: x2w1, x1w2, x1w1
    const int PAI[3] = {1, 0, 0};
    const int PBI[3] = {0, 1, 0};

    const int ptid = tid & 255;
    uint32_t asw_p[4]; size_t aoff_p[4];
    uint32_t bsw_p[2]; size_t boff_p[2];
#pragma unroll
    for (int j = 0; j < 4; j++) {
        int seg = ptid + j * 256;
        int row = seg >> 3, kq = (seg & 7) * 8;
        asw_p[j]  = SWZ((uint32_t)(row * 128 + kq * 2));
        aoff_p[j] = (size_t)(tok0 + row) * HID + kq;
    }
#pragma unroll
    for (int j = 0; j < 2; j++) {
        int seg = ptid + j * 256;
        int row = seg >> 3, kq = (seg & 7) * 8;
        bsw_p[j]  = SWZ((uint32_t)(row * 128 + kq * 2));
        boff_p[j] = (size_t)row * HID + kq;
    }

    float4 av[4][2], bvv[2][2];
    if (producer) {   // prefetch chunk 0
#pragma unroll
        for (int j = 0; j < 4; j++) {
            av[j][0] = *(const float4*)(X + aoff_p[j]);
            av[j][1] = *(const float4*)(X + aoff_p[j] + 4);
        }
#pragma unroll
        for (int j = 0; j < 2; j++) {
            bvv[j][0] = *(const float4*)(W + boff_p[j]);
            bvv[j][1] = *(const float4*)(W + boff_p[j] + 4);
        }
    }

    float hi[2][4][4];
#pragma unroll
    for (int mi = 0; mi < 2; mi++)
#pragma unroll
        for (int j = 0; j < 4; j++)
#pragma unroll
            for (int q = 0; q < 4; q++) hi[mi][j][q] = 0.f;

    for (int it = 0; it <= NCHUNK; it++) {
        if (producer) {
            if (it < NCHUNK) {
                char* base = dsm + (it & 1) * BUFSZ;
#pragma unroll
                for (int j = 0; j < 4; j++)
                    split2_store(base + OF_A1, 16384, asw_p[j], av[j][0], av[j][1], 1.0f);
#pragma unroll
                for (int j = 0; j < 2; j++)
                    split2_store(base + OF_B1, 8192, bsw_p[j], bvv[j][0], bvv[j][1], WSCALE);
                if (it + 1 < NCHUNK) {
                    int k0 = (it + 1) * BKC;
#pragma unroll
                    for (int j = 0; j < 4; j++) {
                        av[j][0] = *(const float4*)(X + aoff_p[j] + k0);
                        av[j][1] = *(const float4*)(X + aoff_p[j] + k0 + 4);
                    }
#pragma unroll
                    for (int j = 0; j < 2; j++) {
                        bvv[j][0] = *(const float4*)(W + boff_p[j] + k0);
                        bvv[j][1] = *(const float4*)(W + boff_p[j] + k0 + 4);
                    }
                }
            }
        } else if (it >= 1) {
            const uint32_t bb = smb + (uint32_t)(((it - 1) & 1) * BUFSZ);
            float accf[2][4][4];
#pragma unroll
            for (int mi = 0; mi < 2; mi++)
#pragma unroll
                for (int j = 0; j < 4; j++)
#pragma unroll
                    for (int q = 0; q < 4; q++) accf[mi][j][q] = 0.f;
#pragma unroll
            for (int ks = 0; ks < 4; ks++) {
                uint32_t kb_a = (uint32_t)(ks * 32) + akoff;
                uint32_t kb_b = (uint32_t)(ks * 32) + bkoff;
                uint32_t afr[2][2][4];      // [split][mi]
                uint32_t bfr[2][2][4];      // [split][jj]
#pragma unroll
                for (int s = 0; s < 2; s++) {
#pragma unroll
                    for (int mi = 0; mi < 2; mi++)
                        ldsm_x4(afr[s][mi], bb + SA[s] + aconst[mi] + (kb_a ^ amask[mi]));
#pragma unroll
                    for (int jj = 0; jj < 2; jj++)
                        ldsm_x4(bfr[s][jj], bb + SB[s] + bconst4[jj] + (kb_b ^ bmask));
                }
#pragma unroll
                for (int p = 0; p < 3; p++)
#pragma unroll
                    for (int mi = 0; mi < 2; mi++)
#pragma unroll
                        for (int j = 0; j < 4; j++)
                            mma_f16(accf[mi][j], afr[PAI[p]][mi],
                                    &bfr[PBI[p]][j >> 1][(j & 1) * 2]);
            }
#pragma unroll
            for (int mi = 0; mi < 2; mi++)
#pragma unroll
                for (int j = 0; j < 4; j++)
#pragma unroll
                    for (int q = 0; q < 4; q++) hi[mi][j][q] += accf[mi][j][q];
        }
        __syncthreads();
    }

    // epilogue: unscale (exact pow2) then exp(logits) into Cs (overlays buf0)
    if (!producer) {
#pragma unroll
        for (int mi = 0; mi < 2; mi++) {
            int r0 = mt * 32 + mi * 16 + (lane >> 2);
#pragma unroll
            for (int j = 0; j < 4; j++) {
                int cc = nh * 32 + j * 8 + (lane & 3) * 2;
                float2 v0 = make_float2(__nv_expf(hi[mi][j][0] * WUNSCALE),
                                        __nv_expf(hi[mi][j][1] * WUNSCALE));
                float2 v1 = make_float2(__nv_expf(hi[mi][j][2] * WUNSCALE),
                                        __nv_expf(hi[mi][j][3] * WUNSCALE));
                *(float2*)&Cs[r0 * NEXP + cc]       = v0;
                *(float2*)&Cs[(r0 + 8) * NEXP + cc] = v1;
            }
        }
    }
    if (tid < NEXP) { d1d[tid] = 1.0; d1pd[tid] = 1.0; d1f[tid] = 1.f; }
    grid_barrier();   // Cs ready; colsum zeros globally visible

    // ================= phase B: Sinkhorn iterations ========================
    const float  INVN0F = 1.0f / (float)NTOK;   // 2^-14 exact
    const float  INVN1F = 0.015625f;            // 2^-6 exact
    const float  EPSF   = 1e-8f;
    const double INVN1D = 1.0 / (double)NEXP;
    const double EPSD   = (double)1e-8f;
    const int    esl    = (tid < NEXP) ? ((tid + (bid << 2)) & 63) : 0;

    for (int it = 0; it < MAX_ITERS; it++) {
        float d1a = d1f[lane];
        float d1c = d1f[lane + 32];
        float p0 = 0.f, p1 = 0.f;
        {   // 8-way interleaved shuffle trees; original accumulation order
            float c0[8], c1[8], s[8];
#pragma unroll
            for (int q = 0; q < 8; q++) {
                int t = w + q * NW;
                c0[q] = Cs[t * NEXP + lane];
                c1[q] = Cs[t * NEXP + lane + 32];
                s[q]  = fmaf(d1a, c0[q], d1c * c1[q]);
            }
#pragma unroll
            for (int off = 16; off; off >>= 1)
#pragma unroll
                for (int q = 0; q < 8; q++)
                    s[q] += __shfl_xor_sync(0xffffffffu, s[q], off);
#pragma unroll
            for (int q = 0; q < 8; q++) {
                float d0 = frcp_approx(s[q] + EPSF) * INVN0F;
                p0 = fmaf(d0, c0[q], p0);
                p1 = fmaf(d0, c1[q], p1);
            }
        }
        warp_part[w][lane]      = p0;
        warp_part[w][lane + 32] = p1;
        __syncthreads();
        if (tid < NEXP) {
            double sum = 0.0;
#pragma unroll
            for (int ww = 0; ww < NW; ww++) sum += (double)warp_part[ww][esl];
            atomicAdd(&g_colsum[((size_t)it * NEXP + esl) * CSTRIDE], sum);
        }
        grid_barrier();

        if (w == 0) {
            double cs0 = g_colsum[((size_t)it * NEXP + lane) * CSTRIDE];
            double cs1 = g_colsum[((size_t)it * NEXP + lane + 32) * CSTRIDE];
            // fast f32 mirror first — unblocks the next row pass ASAP
            d1f[lane]      = frcp_approx((float)cs0 + EPSF) * INVN1F;
            d1f[lane + 32] = frcp_approx((float)cs1 + EPSF) * INVN1F;
            // f64 master via rcp + 2 Newton steps (~1 ulp)
            double x0 = cs0 + EPSD, x1 = cs1 + EPSD;
            double r0 = (double)frcp_approx((float)x0);
            double r1 = (double)frcp_approx((float)x1);
            r0 = r0 * (2.0 - x0 * r0); r0 = r0 * (2.0 - x0 * r0);
            r1 = r1 * (2.0 - x1 * r1); r1 = r1 * (2.0 - x1 * r1);
            double v0 = INVN1D * r0, v1 = INVN1D * r1;
            double o0 = d1d[lane], o1 = d1d[lane + 32];
            double s  = warp_tree_add64(fabs(o0 - v0) + fabs(o1 - v1));
            d1pd[lane]      = o0;  d1pd[lane + 32] = o1;
            d1d[lane]       = v0;  d1d[lane + 32]  = v1;
            if (lane == 0) s_err = s * INVN1D;
        }
        __syncthreads();
        if (s_err <= SINK_TOL) break;
    }

    // ================= phase C: top-2 (fp64) + softmax-gather ==============
    const double INVN0D = 1.0 / (double)NTOK;
    double d1a = d1d[lane],  d1c = d1d[lane + 32];
    double dpa = d1pd[lane], dpc = d1pd[lane + 32];
    for (int t = w; t < TOKB; t += NW) {
        double c0 = (double)Cs[t * NEXP + lane];
        double c1 = (double)Cs[t * NEXP + lane + 32];
        double sr = warp_tree_add64(dpa * c0 + dpc * c1);
        double rs = warp_tree_add64(c0 + c1);
        double d0 = INVN0D / (sr + EPSD);
        double v0 = (d1a * c0) * d0;
        double v1 = (d1c * c1) * d0;

        double mv; int mi;
        if (v0 >= v1) { mv = v0; mi = lane; } else { mv = v1; mi = lane + 32; }
#pragma unroll
        for (int off = 16; off; off >>= 1) {
            double ov = __shfl_xor_sync(0xffffffffu, mv, off);
            int    oi = __shfl_xor_sync(0xffffffffu, mi, off);
            if (ov > mv || (ov == mv && oi < mi)) { mv = ov; mi = oi; }
        }
        double u0 = (lane      == mi) ? -1e308 : v0;
        double u1 = (lane + 32 == mi) ? -1e308 : v1;
        double mv2; int mi2;
        if (u0 >= u1) { mv2 = u0; mi2 = lane; } else { mv2 = u1; mi2 = lane + 32; }
#pragma unroll
        for (int off = 16; off; off >>= 1) {
            double ov = __shfl_xor_sync(0xffffffffu, mv2, off);
            int    oi = __shfl_xor_sync(0xffffffffu, mi2, off);
            if (ov > mv2 || (ov == mv2 && oi < mi2)) { mv2 = ov; mi2 = oi; }
        }

        if (lane == 0) {
            int tg = tok0 + t;
            float s0 = (float)((double)Cs[t * NEXP + mi]  / rs);
            float s1 = (float)((double)Cs[t * NEXP + mi2] / rs);
            if (out_size >= 4 * NTOK) {
                out[(size_t)tg * 2 + 0] = s0;
                out[(size_t)tg * 2 + 1] = s1;
                out[(size_t)2 * NTOK + tg * 2 + 0] = (float)mi;
                out[(size_t)2 * NTOK + tg * 2 + 1] = (float)mi2;
            } else {
                out[(size_t)tg * 2 + 0] = s0;
                out[(size_t)tg * 2 + 1] = s1;
            }
        }
    }
}

// ---------------------------------------------------------------------------
extern "C" void kernel_launch(void* const* d_in, const int* in_sizes, int n_in,
                              void* d_out, int out_size)
{
    const float* X = (const float*)d_in[0];
    const float* W = (const float*)d_in[1];
    if (n_in >= 2 && in_sizes[0] == NEXP * HID) {   // defensive input-order check
        X = (const float*)d_in[1];
        W = (const float*)d_in[0];
    }
    cudaFuncSetAttribute(fused_router_kernel,
                         cudaFuncAttributeMaxDynamicSharedMemorySize, DSM_TOTAL);
    fused_router_kernel<<<GRIDB, TPB, DSM_TOTAL>>>(X, W, (float*)d_out, out_size);
}